// round 17
// baseline (speedup 1.0000x reference)
#include <cuda_runtime.h>
#include <math.h>

// Problem constants (fixed by setup_inputs)
#define NN   50000
#define EE   800000
#define FF   128
#define HH   64
#define CC   16
#define KG   8          // gaussian kernels
#define SCAN_B 256
#define SCAN_NB ((NN + SCAN_B - 1) / SCAN_B)   // 196

// ---------------- scratch (static device globals; no allocation) -------------
// RULE (hard-won): NEVER pass these symbols as kernel arguments from host
// code. On GB300 (ATS) the host-shadow address silently aliases host memory.
// Reference them INSIDE kernel bodies only.
__device__ int   g_rows[EE];
__device__ int   g_cols[EE];
__device__ int   g_cnt[NN];      // in-degree (for mean)
__device__ int   g_rcnt[NN];     // out-degree histogram (for CSR)
__device__ int   g_pos[NN];      // scan output / scatter cursor -> row end
__device__ int   g_bsum[SCAN_NB];
__device__ int   g_boff[SCAN_NB];
__device__ int4  g_epack[EE];    // row-sorted edge payload {col, p0, p1, -}
__device__ int   g_idx64;
__device__ float g_gx1[(size_t)NN * KG * HH];   // x @ g1_w    [N][512]
__device__ float g_r1 [(size_t)NN * HH];        // x @ root1_w [N][64]
__device__ float g_agg1[NN * HH];
__device__ float g_h[NN * HH];
__device__ float g_gx2[(size_t)NN * KG * CC];   // h @ g2_w    [N][128]
__device__ float g_agg2[NN * CC];

// ---------------- dtype detect (warp-parallel) --------------------------------
__global__ void detect_kernel(const int* __restrict__ ei_words) {
    int t = threadIdx.x;           // 32 threads
    int nz = 0;
    for (int i = t; i < 128; i += 32) nz |= (ei_words[2 * i + 1] != 0);
    unsigned m = __ballot_sync(0xffffffffu, nz);
    if (t == 0) g_idx64 = (m == 0);
}

// ---------------- zero accumulators ------------------------------------------
__global__ void zero_kernel(int N) {
    int i = blockIdx.x * blockDim.x + threadIdx.x;
    if (i < N * HH) g_agg1[i] = 0.f;
    if (i < N * CC) g_agg2[i] = 0.f;
    if (i < N) { g_cnt[i] = 0; g_rcnt[i] = 0; }
}

// ---------------- edge index normalization + degree counts -------------------
__global__ void convert_edges(const void* __restrict__ ei, int E) {
    int e = blockIdx.x * blockDim.x + threadIdx.x;
    if (e >= E) return;
    int r, c;
    if (g_idx64) {
        const long long* p = (const long long*)ei;
        r = (int)p[e];
        c = (int)p[(size_t)E + e];
    } else {
        const int* p = (const int*)ei;
        r = p[e];
        c = p[E + e];
    }
    g_rows[e] = r;
    g_cols[e] = c;
    atomicAdd(&g_cnt[c], 1);
    atomicAdd(&g_rcnt[r], 1);
}

// ---------------- multi-block exclusive scan of g_rcnt -> g_pos --------------
__global__ __launch_bounds__(SCAN_B) void scanA_kernel(int N) {
    __shared__ int sh[SCAN_B];
    int t = threadIdx.x;
    int i = blockIdx.x * SCAN_B + t;
    sh[t] = (i < N) ? g_rcnt[i] : 0;
    __syncthreads();
    for (int off = SCAN_B / 2; off > 0; off >>= 1) {
        if (t < off) sh[t] += sh[t + off];
        __syncthreads();
    }
    if (t == 0) g_bsum[blockIdx.x] = sh[0];
}
__global__ __launch_bounds__(SCAN_B) void scanB_kernel() {
    __shared__ int sh[SCAN_B];
    int t = threadIdx.x;
    sh[t] = (t < SCAN_NB) ? g_bsum[t] : 0;
    __syncthreads();
    for (int off = 1; off < SCAN_B; off <<= 1) {
        int v = (t >= off) ? sh[t - off] : 0;
        __syncthreads();
        sh[t] += v;
        __syncthreads();
    }
    if (t < SCAN_NB) g_boff[t] = sh[t] - g_bsum[t];   // exclusive
}
__global__ __launch_bounds__(SCAN_B) void scanC_kernel(int N) {
    __shared__ int sh[SCAN_B];
    int t = threadIdx.x;
    int i = blockIdx.x * SCAN_B + t;
    int own = (i < N) ? g_rcnt[i] : 0;
    sh[t] = own;
    __syncthreads();
    for (int off = 1; off < SCAN_B; off <<= 1) {
        int v = (t >= off) ? sh[t - off] : 0;
        __syncthreads();
        sh[t] += v;
        __syncthreads();
    }
    if (i < N) g_pos[i] = g_boff[blockIdx.x] + sh[t] - own;  // exclusive start
}

// ---------------- scatter edges into row-sorted packed SoA -------------------
// After this kernel g_pos[r] == row end (start[r] = g_pos[r] - g_rcnt[r]).
__global__ void sort_kernel(const float* __restrict__ ea, int E) {
    int e = blockIdx.x * blockDim.x + threadIdx.x;
    if (e >= E) return;
    int r = g_rows[e], c = g_cols[e];
    int pos = atomicAdd(&g_pos[r], 1);
    int4 q;
    q.x = c;
    q.y = __float_as_int(ea[2 * (size_t)e]);
    q.z = __float_as_int(ea[2 * (size_t)e + 1]);
    q.w = 0;
    g_epack[pos] = q;
}

// ---------------- smem-tiled GEMM, double-buffered ---------------------------
// BM=128, BN=64, BK=16, 256 threads, 8x4 microtile, 2-stage smem pipeline
// (one __syncthreads per K-tile; LDG for tile i+1 issued before computing
// tile i, STS after compute). MODE selects device-global operands IN-KERNEL.
template <int MODE>
__global__ __launch_bounds__(256) void gemm_tile(const float* __restrict__ Aarg,
                                                 const float* __restrict__ B,
                                                 int M, int N, int K) {
    const float* A = (MODE == 2) ? (const float*)g_h : Aarg;
    float* C = (MODE == 0) ? g_gx1 : (MODE == 1) ? g_r1 : g_gx2;

    const int bm = blockIdx.y * 128;
    const int bn = blockIdx.x * 64;
    __shared__ float sA[2][16][128];
    __shared__ float sB[2][16][64];
    const int t = threadIdx.x;
    const int mt = (t >> 4) << 3;
    const int nt = (t & 15) << 2;
    const int la_m = t >> 1;
    const int la_k = (t & 1) << 3;
    const int lb_k = t >> 4;
    const int lb_n = (t & 15) << 2;

    const bool arow_ok = (bm + la_m) < M;
    const float* Aptr = A + (size_t)(bm + la_m) * K + la_k;
    float acc[8][4] = {};

    // prologue: tile 0 -> buffer 0
    {
        float4 a4 = make_float4(0.f, 0.f, 0.f, 0.f);
        float4 a4b = make_float4(0.f, 0.f, 0.f, 0.f);
        if (arow_ok) {
            a4  = *(const float4*)(Aptr);
            a4b = *(const float4*)(Aptr + 4);
        }
        sA[0][la_k + 0][la_m] = a4.x;
        sA[0][la_k + 1][la_m] = a4.y;
        sA[0][la_k + 2][la_m] = a4.z;
        sA[0][la_k + 3][la_m] = a4.w;
        sA[0][la_k + 4][la_m] = a4b.x;
        sA[0][la_k + 5][la_m] = a4b.y;
        sA[0][la_k + 6][la_m] = a4b.z;
        sA[0][la_k + 7][la_m] = a4b.w;
        *(float4*)&sB[0][lb_k][lb_n] =
            *(const float4*)(B + (size_t)lb_k * N + bn + lb_n);
    }
    __syncthreads();

    const int niter = K >> 4;
    for (int it = 0; it < niter; it++) {
        int cur = it & 1, nxt = cur ^ 1;
        bool hasnext = (it + 1) < niter;
        float4 a4 = make_float4(0.f, 0.f, 0.f, 0.f);
        float4 a4b = make_float4(0.f, 0.f, 0.f, 0.f);
        float4 b4 = make_float4(0.f, 0.f, 0.f, 0.f);
        if (hasnext) {
            int k0 = (it + 1) << 4;
            if (arow_ok) {
                a4  = *(const float4*)(Aptr + k0);
                a4b = *(const float4*)(Aptr + k0 + 4);
            }
            b4 = *(const float4*)(B + (size_t)(k0 + lb_k) * N + bn + lb_n);
        }
#pragma unroll
        for (int kk = 0; kk < 16; kk++) {
            float4 a_lo = *(const float4*)&sA[cur][kk][mt];
            float4 a_hi = *(const float4*)&sA[cur][kk][mt + 4];
            float4 b = *(const float4*)&sB[cur][kk][nt];
            float ra[8] = {a_lo.x, a_lo.y, a_lo.z, a_lo.w,
                           a_hi.x, a_hi.y, a_hi.z, a_hi.w};
#pragma unroll
            for (int i = 0; i < 8; i++) {
                acc[i][0] += ra[i] * b.x;
                acc[i][1] += ra[i] * b.y;
                acc[i][2] += ra[i] * b.z;
                acc[i][3] += ra[i] * b.w;
            }
        }
        if (hasnext) {
            sA[nxt][la_k + 0][la_m] = a4.x;
            sA[nxt][la_k + 1][la_m] = a4.y;
            sA[nxt][la_k + 2][la_m] = a4.z;
            sA[nxt][la_k + 3][la_m] = a4.w;
            sA[nxt][la_k + 4][la_m] = a4b.x;
            sA[nxt][la_k + 5][la_m] = a4b.y;
            sA[nxt][la_k + 6][la_m] = a4b.z;
            sA[nxt][la_k + 7][la_m] = a4b.w;
            *(float4*)&sB[nxt][lb_k][lb_n] = b4;
        }
        __syncthreads();
    }
#pragma unroll
    for (int i = 0; i < 8; i++) {
        int r = bm + mt + i;
        if (r < M) {
            float4 o = make_float4(acc[i][0], acc[i][1], acc[i][2], acc[i][3]);
            *(float4*)(C + (size_t)r * N + bn + nt) = o;
        }
    }
}

// ---------------- edge stage 1: WARP per SOURCE NODE (CSR, packed) -----------
__global__ __launch_bounds__(256) void edge1_csr(const float* __restrict__ mu1,
                                                 const float* __restrict__ sig1,
                                                 int N) {
    int r = (blockIdx.x * blockDim.x + threadIdx.x) >> 5;
    int lane = threadIdx.x & 31;
    if (r >= N) return;
    int end = g_pos[r];
    int start = end - g_rcnt[r];
    if (start == end) return;

    const float2* gx = (const float2*)(g_gx1 + (size_t)r * (KG * HH));
    float2 v[KG];
#pragma unroll
    for (int k = 0; k < KG; k++) v[k] = gx[k * 32 + lane];

    float mx = 0.f, my = 0.f, ivx = 0.f, ivy = 0.f;
    if (lane < KG) {
        mx = mu1[lane * 2]; my = mu1[lane * 2 + 1];
        float sx = sig1[lane * 2], sy = sig1[lane * 2 + 1];
        ivx = 0.5f / (1e-15f + sx * sx);
        ivy = 0.5f / (1e-15f + sy * sy);
    }

    for (int e = start; e < end; e++) {
        int4 q = g_epack[e];
        int c = q.x;
        float p0 = __int_as_float(q.y);
        float p1 = __int_as_float(q.z);
        float g = 0.f;
        if (lane < KG) {
            float dx = p0 - mx, dy = p1 - my;
            g = expf(-(dx * dx * ivx + dy * dy * ivy));
        }
        float ax = 0.f, ay = 0.f;
#pragma unroll
        for (int k = 0; k < KG; k++) {
            float gk = __shfl_sync(0xffffffffu, g, k);
            ax += gk * v[k].x;
            ay += gk * v[k].y;
        }
        float* dst = g_agg1 + (size_t)c * HH + 2 * lane;
        asm volatile("red.global.add.v2.f32 [%0], {%1, %2};" ::"l"(dst),
                     "f"(ax), "f"(ay) : "memory");
    }
}

// ---------------- node stage 1: mean + precomputed root + bias + elu ---------
__global__ void node1_kernel(const float* __restrict__ bias1, int N) {
    int i = blockIdx.x * blockDim.x + threadIdx.x;
    if (i >= N * HH) return;
    int n = i >> 6, o = i & 63;
    float cnt = fmaxf((float)g_cnt[n], 1.0f);
    float v = g_agg1[i] / cnt + g_r1[i] + bias1[o];
    g_h[i] = v > 0.f ? v : expm1f(v);
}

// ---------------- edge stage 2: WARP per SOURCE NODE, 4 edges/iter -----------
__global__ __launch_bounds__(256) void edge2_csr(const float* __restrict__ mu2,
                                                 const float* __restrict__ sig2,
                                                 int N) {
    int r = (blockIdx.x * blockDim.x + threadIdx.x) >> 5;
    int lane = threadIdx.x & 31;
    if (r >= N) return;
    int end = g_pos[r];
    int start = end - g_rcnt[r];
    if (start == end) return;

    int sub = lane & 7, grp = lane >> 3;

    const float2* gx = (const float2*)(g_gx2 + (size_t)r * (KG * CC));
    float2 v[KG];
#pragma unroll
    for (int k = 0; k < KG; k++) v[k] = gx[k * 8 + sub];

    float mx = mu2[sub * 2], my = mu2[sub * 2 + 1];
    float sx = sig2[sub * 2], sy = sig2[sub * 2 + 1];
    float ivx = 0.5f / (1e-15f + sx * sx);
    float ivy = 0.5f / (1e-15f + sy * sy);

    for (int e0 = start; e0 < end; e0 += 4) {
        int eh = e0 + grp;
        bool val = (eh < end);
        int c = 0;
        float g = 0.f;
        if (val) {
            int4 q = g_epack[eh];
            c = q.x;
            float dx = __int_as_float(q.y) - mx, dy = __int_as_float(q.z) - my;
            g = expf(-(dx * dx * ivx + dy * dy * ivy));
        }
        float ax = 0.f, ay = 0.f;
#pragma unroll
        for (int k = 0; k < KG; k++) {
            float gk = __shfl_sync(0xffffffffu, g, (grp << 3) + k);
            ax += gk * v[k].x;
            ay += gk * v[k].y;
        }
        if (val) {
            float* dst = g_agg2 + (size_t)c * CC + 2 * sub;
            asm volatile("red.global.add.v2.f32 [%0], {%1, %2};" ::"l"(dst),
                         "f"(ax), "f"(ay) : "memory");
        }
    }
}

// ---------------- node stage 2: mean + inline root + bias + log_softmax ------
__global__ void node2_kernel(const float* __restrict__ root2,
                             const float* __restrict__ bias2,
                             float* __restrict__ out, int N) {
    int n = blockIdx.x * blockDim.x + threadIdx.x;
    if (n >= N) return;
    float cnt = fmaxf((float)g_cnt[n], 1.0f);
    float vals[CC];
    float m = -1e30f;
    for (int c = 0; c < CC; c++) {
        float root = 0.f;
        for (int f = 0; f < HH; f++)
            root += g_h[(size_t)n * HH + f] * root2[(size_t)f * CC + c];
        float v = g_agg2[(size_t)n * CC + c] / cnt + root + bias2[c];
        vals[c] = v;
        m = fmaxf(m, v);
    }
    float s = 0.f;
    for (int c = 0; c < CC; c++) s += expf(vals[c] - m);
    float lse = m + logf(s);
    for (int c = 0; c < CC; c++) out[(size_t)n * CC + c] = vals[c] - lse;
}

// ---------------- launch -----------------------------------------------------
extern "C" void kernel_launch(void* const* d_in, const int* in_sizes, int n_in,
                              void* d_out, int out_size) {
    const float* x      = (const float*)d_in[0];
    const void*  ei     = d_in[1];
    const float* ea     = (const float*)d_in[2];
    const float* g1_w   = (const float*)d_in[3];
    const float* mu1    = (const float*)d_in[4];
    const float* sig1   = (const float*)d_in[5];
    const float* root1  = (const float*)d_in[6];
    const float* bias1  = (const float*)d_in[7];
    const float* g2_w   = (const float*)d_in[8];
    const float* mu2    = (const float*)d_in[9];
    const float* sig2   = (const float*)d_in[10];
    const float* root2  = (const float*)d_in[11];
    const float* bias2  = (const float*)d_in[12];
    float* out = (float*)d_out;

    int N = in_sizes[0] / FF;       // 50000
    int E = in_sizes[2] / 2;        // 800000
    int mb = (N + 127) / 128;       // 391

    // one-time side stream + events (created on the UNCAPTURED correctness
    // call, reused during graph capture -> standard fork/join capture pattern)
    static cudaStream_t s1 = nullptr;
    static cudaEvent_t evFork = nullptr, evG0 = nullptr, evR1 = nullptr;
    if (!s1) {
        cudaStreamCreateWithFlags(&s1, cudaStreamNonBlocking);
        cudaEventCreateWithFlags(&evFork, cudaEventDisableTiming);
        cudaEventCreateWithFlags(&evG0, cudaEventDisableTiming);
        cudaEventCreateWithFlags(&evR1, cudaEventDisableTiming);
    }

    // fork: gemm0 then r1 on s1; prep chain on the main stream
    cudaEventRecord(evFork, 0);
    cudaStreamWaitEvent(s1, evFork, 0);
    gemm_tile<0><<<dim3(512 / 64, mb), 256, 0, s1>>>(x, g1_w, N, 512, FF);
    cudaEventRecord(evG0, s1);
    gemm_tile<1><<<dim3(64 / 64, mb), 256, 0, s1>>>(x, root1, N, 64, FF);
    cudaEventRecord(evR1, s1);

    detect_kernel<<<1, 32>>>((const int*)ei);
    zero_kernel<<<(N * HH + 255) / 256, 256>>>(N);
    convert_edges<<<(E + 255) / 256, 256>>>(ei, E);
    scanA_kernel<<<SCAN_NB, SCAN_B>>>(N);
    scanB_kernel<<<1, SCAN_B>>>();
    scanC_kernel<<<SCAN_NB, SCAN_B>>>(N);
    sort_kernel<<<(E + 255) / 256, 256>>>(ea, E);

    // edge1 needs sort (main) + gemm0 (s1); r1 only needed by node1
    cudaStreamWaitEvent(0, evG0, 0);
    edge1_csr<<<(N + 7) / 8, 256>>>(mu1, sig1, N);
    cudaStreamWaitEvent(0, evR1, 0);
    node1_kernel<<<(N * HH + 255) / 256, 256>>>(bias1, N);

    // layer 2 (sequential dependency chain on main stream)
    gemm_tile<2><<<dim3(128 / 64, mb), 256>>>(nullptr, g2_w, N, 128, HH);
    edge2_csr<<<(N + 7) / 8, 256>>>(mu2, sig2, N);
    node2_kernel<<<(N + 255) / 256, 256>>>(root2, bias2, out, N);
}